// round 2
// baseline (speedup 1.0000x reference)
#include <cuda_runtime.h>
#include <cstdint>

#define D        256
#define BD       16384
#define TILE_M   32
#define ROWSTR   264            // 256 + 8 floats pad
#define NTHR     256
#define NCTA     (BD / TILE_M)  // 512
#define L_STEPS  6
#define NFX_IT   8
#define HGAM     0.005f         // gamma/2
#define BUF_ELEMS (TILE_M * ROWSTR)
#define NBUF     5
#define SMEM_BYTES ((NBUF * BUF_ELEMS + D) * 4)

__device__ float g_WT[D * D];

__global__ void wt_kernel(const float* __restrict__ W) {
  int j = blockIdx.x, i = threadIdx.x;
  g_WT[j * D + i] = W[i * D + j];
}

__device__ __forceinline__ float frcp(float x) {
  float r; asm("rcp.approx.f32 %0, %1;" : "=f"(r) : "f"(x)); return r;
}
__device__ __forceinline__ unsigned long long pack2(float x) {
  unsigned long long r; unsigned u = __float_as_uint(x);
  asm("mov.b64 %0, {%1, %1};" : "=l"(r) : "r"(u)); return r;
}
__device__ __forceinline__ void fma2(unsigned long long& d, unsigned long long a,
                                     unsigned long long b) {
  asm("fma.rn.f32x2 %0, %1, %2, %0;" : "+l"(d) : "l"(a), "l"(b));
}

// stable sigmoid + softplus
__device__ __forceinline__ void sigsp(float x, float& sg, float& sp) {
  float ax = fabsf(x);
  float e  = __expf(-ax);
  float p  = 1.0f + e;
  float rp = frcp(p);
  sg = (x >= 0.0f) ? rp : e * rp;
  sp = fmaxf(x, 0.0f) + __logf(p);
}
__device__ __forceinline__ float softplus_f(float x) {
  return fmaxf(x, 0.0f) + __logf(1.0f + __expf(-fabsf(x)));
}

union F4 { float4 v; float f[4]; };

__device__ __forceinline__ float4* p4(float* b, int m, int j) {
  return reinterpret_cast<float4*>(b + m * ROWSTR + j);
}
__device__ __forceinline__ const float4* p4c(const float* b, int m, int j) {
  return reinterpret_cast<const float4*>(b + m * ROWSTR + j);
}

// out[m][j] = sum_i xs[m][i] * Wg[i][j]   (M=32 tile, Wg row-major 256x256 in L2)
// warp w -> rows m0=4w..4w+3, lane -> cols j0=8*lane..+7
__device__ __forceinline__ void gemm32(const float* __restrict__ Wg,
                                       const float* __restrict__ xs,
                                       float acc[4][8]) {
  const int lane = threadIdx.x & 31;
  const int m0   = (threadIdx.x >> 5) << 2;
  unsigned long long a2[4][4];
#pragma unroll
  for (int r = 0; r < 4; r++)
#pragma unroll
    for (int c = 0; c < 4; c++) a2[r][c] = 0ull;

  const longlong2* W2 = reinterpret_cast<const longlong2*>(Wg);
#pragma unroll 2
  for (int i4 = 0; i4 < 64; i4++) {
    float4 xv[4];
#pragma unroll
    for (int r = 0; r < 4; r++)
      xv[r] = *reinterpret_cast<const float4*>(xs + (m0 + r) * ROWSTR + i4 * 4);
#pragma unroll
    for (int ii = 0; ii < 4; ii++) {
      const int i = i4 * 4 + ii;
      longlong2 wa = __ldg(&W2[i * 64 + lane * 2]);
      longlong2 wb = __ldg(&W2[i * 64 + lane * 2 + 1]);
#pragma unroll
      for (int r = 0; r < 4; r++) {
        float xr = (ii == 0) ? xv[r].x : (ii == 1) ? xv[r].y
                 : (ii == 2) ? xv[r].z : xv[r].w;
        unsigned long long xx = pack2(xr);
        fma2(a2[r][0], xx, (unsigned long long)wa.x);
        fma2(a2[r][1], xx, (unsigned long long)wa.y);
        fma2(a2[r][2], xx, (unsigned long long)wb.x);
        fma2(a2[r][3], xx, (unsigned long long)wb.y);
      }
    }
  }
#pragma unroll
  for (int r = 0; r < 4; r++)
#pragma unroll
    for (int c = 0; c < 4; c++) {
      unsigned lo, hi;
      asm("mov.b64 {%0,%1}, %2;" : "=r"(lo), "=r"(hi) : "l"(a2[r][c]));
      acc[r][2 * c]     = __uint_as_float(lo);
      acc[r][2 * c + 1] = __uint_as_float(hi);
    }
}

// Buffer roles (5 x BUF_ELEMS):
//   slots {0,3}: z-role / softplus-role, toggle each leapfrog step
//   slot 1: VHb  (v_half; equals v at step start, v_new at step end)
//   slot 2: Hb   (h = 0.5*sigma/softplus at current z)
//   slot 4: Ub   (GEMM input workspace / cst)
__global__ void __launch_bounds__(NTHR, 1)
rhmc_kernel(const float* __restrict__ z0, const float* __restrict__ v0,
            const float* __restrict__ W, const float* __restrict__ bias,
            float* __restrict__ out) {
  extern __shared__ float smf[];
  float* B0  = smf;
  float* bsh = smf + NBUF * BUF_ELEMS;
  const int tid  = threadIdx.x;
  const int lane = tid & 31;
  const int m0   = (tid >> 5) << 2;
  const int j0   = lane << 3;
  const int row0 = blockIdx.x * TILE_M;

  int zi = 0, spi = 3;
  float* VHb = B0 + 1 * BUF_ELEMS;
  float* Hb  = B0 + 2 * BUF_ELEMS;
  float* Ub  = B0 + 4 * BUF_ELEMS;

  bsh[tid] = bias[tid];
  for (int idx = tid; idx < TILE_M * D; idx += NTHR) {
    int m = idx >> 8, i = idx & 255;
    B0[zi * BUF_ELEMS + m * ROWSTR + i] = z0[(row0 + m) * D + i];
    VHb[m * ROWSTR + i] = v0[(row0 + m) * D + i];
  }
  __syncthreads();

  float acc[4][8];

  // initial: a = z0@W + b -> sp into slot(spi), h into Hb
  gemm32(W, B0 + zi * BUF_ELEMS, acc);
  {
    float* Sb = B0 + spi * BUF_ELEMS;
#pragma unroll
    for (int r = 0; r < 4; r++)
#pragma unroll
      for (int h4 = 0; h4 < 2; h4++) {
        F4 bb; bb.v = *reinterpret_cast<const float4*>(bsh + j0 + 4 * h4);
        F4 osp, oh;
#pragma unroll
        for (int c = 0; c < 4; c++) {
          float x = acc[r][4 * h4 + c] + bb.f[c];
          float sg, sp; sigsp(x, sg, sp);
          osp.f[c] = sp;
          oh.f[c]  = 0.5f * sg * frcp(fmaxf(sp, 1e-12f));
        }
        *p4(Sb, m0 + r, j0 + 4 * h4) = osp.v;
        *p4(Hb, m0 + r, j0 + 4 * h4) = oh.v;
      }
  }

  for (int l = 0; l < L_STEPS; l++) {
    float* Zb = B0 + zi  * BUF_ELEMS;   // z
    float* Sb = B0 + spi * BUF_ELEMS;   // softplus(a(z))

    // ---- A: cumulative velocity iteration: vh <- vh - g/2 * dH_dz(z, vh)
    for (int k = 0; k < NFX_IT; k++) {
      __syncthreads();
      for (int idx = tid; idx < TILE_M * D; idx += NTHR) {
        int off = ((idx >> 8) * ROWSTR) + (idx & 255);
        float vh = VHb[off];
        Ub[off] = Hb[off] * (Sb[off] * vh * vh - 1.0f);   // u = 0.5*sig*vh^2 - h
      }
      __syncthreads();
      gemm32(g_WT, Ub, acc);                              // dH_dz = u @ W^T
#pragma unroll
      for (int r = 0; r < 4; r++)
#pragma unroll
        for (int h4 = 0; h4 < 2; h4++) {
          F4 vv; vv.v = *p4c(VHb, m0 + r, j0 + 4 * h4);
          F4 o;
#pragma unroll
          for (int c = 0; c < 4; c++) o.f[c] = vv.f[c] - HGAM * acc[r][4 * h4 + c];
          *p4(VHb, m0 + r, j0 + 4 * h4) = o.v;
        }
    }
    __syncthreads();

    // ---- B1: c = vh@W + b -> w = sigmoid(c)/softplus(c) into Ub
    gemm32(W, VHb, acc);
#pragma unroll
    for (int r = 0; r < 4; r++)
#pragma unroll
      for (int h4 = 0; h4 < 2; h4++) {
        F4 bb; bb.v = *reinterpret_cast<const float4*>(bsh + j0 + 4 * h4);
        F4 o;
#pragma unroll
        for (int c = 0; c < 4; c++) {
          float x = acc[r][4 * h4 + c] + bb.f[c];
          float sg, sp; sigsp(x, sg, sp);
          o.f[c] = sg * frcp(fmaxf(sp, 1e-12f));
        }
        *p4(Ub, m0 + r, j0 + 4 * h4) = o.v;
      }
    __syncthreads();

    // ---- B2: rr = w@W^T ; cst = g/2*(sp(z)*vh - rr) into Ub ; zn(=z) into Sb
    gemm32(g_WT, Ub, acc);
    __syncthreads();                  // Ub fully consumed before overwrite
#pragma unroll
    for (int r = 0; r < 4; r++)
#pragma unroll
      for (int h4 = 0; h4 < 2; h4++) {
        F4 zz; zz.v = *p4c(Zb,  m0 + r, j0 + 4 * h4);
        F4 ss; ss.v = *p4c(Sb,  m0 + r, j0 + 4 * h4);
        F4 vh; vh.v = *p4c(VHb, m0 + r, j0 + 4 * h4);
        F4 oc, oz;
#pragma unroll
        for (int c = 0; c < 4; c++) {
          oc.f[c] = HGAM * (ss.f[c] * vh.f[c] - acc[r][4 * h4 + c]);
          oz.f[c] = zz.f[c];
        }
        *p4(Ub, m0 + r, j0 + 4 * h4) = oc.v;   // cst (re-added every iter)
        *p4(Sb, m0 + r, j0 + 4 * h4) = oz.v;   // zn starts at z
      }

    // ---- C: cumulative position iteration: zn += cst + g/2*sp(zn@W+b)*vh
    for (int k = 0; k < NFX_IT; k++) {
      __syncthreads();
      gemm32(W, Sb, acc);                       // an = zn@W
      __syncthreads();                          // Sb fully read before update
#pragma unroll
      for (int r = 0; r < 4; r++)
#pragma unroll
        for (int h4 = 0; h4 < 2; h4++) {
          F4 bb; bb.v = *reinterpret_cast<const float4*>(bsh + j0 + 4 * h4);
          F4 zn; zn.v = *p4c(Sb,  m0 + r, j0 + 4 * h4);
          F4 cc; cc.v = *p4c(Ub,  m0 + r, j0 + 4 * h4);
          F4 vh; vh.v = *p4c(VHb, m0 + r, j0 + 4 * h4);
          F4 o;
#pragma unroll
          for (int c = 0; c < 4; c++) {
            float sp = softplus_f(acc[r][4 * h4 + c] + bb.f[c]);
            o.f[c] = zn.f[c] + cc.f[c] + HGAM * sp * vh.f[c];
          }
          *p4(Sb, m0 + r, j0 + 4 * h4) = o.v;
        }
    }
    __syncthreads();

    // ---- D1: a(z_new) -> sp into Zb-slot, h into Hb, u into Ub
    gemm32(W, Sb, acc);
    __syncthreads();                            // Sb fully read before Ub write
#pragma unroll
    for (int r = 0; r < 4; r++)
#pragma unroll
      for (int h4 = 0; h4 < 2; h4++) {
        F4 bb; bb.v = *reinterpret_cast<const float4*>(bsh + j0 + 4 * h4);
        F4 vh; vh.v = *p4c(VHb, m0 + r, j0 + 4 * h4);
        F4 osp, oh, ou;
#pragma unroll
        for (int c = 0; c < 4; c++) {
          float x = acc[r][4 * h4 + c] + bb.f[c];
          float sg, sp; sigsp(x, sg, sp);
          float h = 0.5f * sg * frcp(fmaxf(sp, 1e-12f));
          osp.f[c] = sp;
          oh.f[c]  = h;
          ou.f[c]  = h * (sp * vh.f[c] * vh.f[c] - 1.0f);
        }
        *p4(Zb, m0 + r, j0 + 4 * h4) = osp.v;   // Zb-slot becomes sp-role
        *p4(Hb, m0 + r, j0 + 4 * h4) = oh.v;
        *p4(Ub, m0 + r, j0 + 4 * h4) = ou.v;
      }
    __syncthreads();

    // ---- D2: v_new = vh - g/2 * (u@W^T) -> VHb
    gemm32(g_WT, Ub, acc);
#pragma unroll
    for (int r = 0; r < 4; r++)
#pragma unroll
      for (int h4 = 0; h4 < 2; h4++) {
        F4 vh; vh.v = *p4c(VHb, m0 + r, j0 + 4 * h4);
        F4 o;
#pragma unroll
        for (int c = 0; c < 4; c++) o.f[c] = vh.f[c] - HGAM * acc[r][4 * h4 + c];
        *p4(VHb, m0 + r, j0 + 4 * h4) = o.v;
      }

    // rotate roles: z <- zn slot (spi), sp(z_new) is in old zi slot
    int t = zi; zi = spi; spi = t;
  }
  __syncthreads();

  // ---- output: stack([z_f, v_f])
  float* Zf = B0 + zi * BUF_ELEMS;
  for (int idx = tid; idx < TILE_M * D; idx += NTHR) {
    int m = idx >> 8, i = idx & 255;
    out[(row0 + m) * D + i]          = Zf[m * ROWSTR + i];
    out[BD * D + (row0 + m) * D + i] = VHb[m * ROWSTR + i];
  }
}

extern "C" void kernel_launch(void* const* d_in, const int* in_sizes, int n_in,
                              void* d_out, int out_size) {
  const float* z0   = (const float*)d_in[0];
  const float* v0   = (const float*)d_in[1];
  const float* W    = (const float*)d_in[2];
  const float* bias = (const float*)d_in[3];
  float* out = (float*)d_out;

  cudaFuncSetAttribute(rhmc_kernel, cudaFuncAttributeMaxDynamicSharedMemorySize,
                       SMEM_BYTES);

  wt_kernel<<<D, D>>>(W);
  rhmc_kernel<<<NCTA, NTHR, SMEM_BYTES>>>(z0, v0, W, bias, out);
}

// round 6
// speedup vs baseline: 1.3593x; 1.3593x over previous
#include <cuda_runtime.h>
#include <cstdint>

#define D        256
#define BD       16384
#define TILE_M   32
#define ROWSTR   264            // 256 + 8 floats pad
#define NTHR     256
#define NCTA     (BD / TILE_M)  // 512
#define L_STEPS  6
#define NFX_IT   8
#define HGAM     0.005f         // gamma/2
#define BUF_ELEMS (TILE_M * ROWSTR)
#define NBUF     5
#define SMEM_BYTES ((NBUF * BUF_ELEMS + D) * 4)

__device__ float g_WT[D * D];

__global__ void wt_kernel(const float* __restrict__ W) {
  int j = blockIdx.x, i = threadIdx.x;
  g_WT[j * D + i] = W[i * D + j];
}

__device__ __forceinline__ float frcp(float x) {
  float r; asm("rcp.approx.f32 %0, %1;" : "=f"(r) : "f"(x)); return r;
}
__device__ __forceinline__ unsigned long long pack2(float x) {
  unsigned long long r; unsigned u = __float_as_uint(x);
  asm("mov.b64 %0, {%1, %1};" : "=l"(r) : "r"(u)); return r;
}
__device__ __forceinline__ void fma2(unsigned long long& d, unsigned long long a,
                                     unsigned long long b) {
  asm("fma.rn.f32x2 %0, %1, %2, %0;" : "+l"(d) : "l"(a), "l"(b));
}

// stable sigmoid + softplus
__device__ __forceinline__ void sigsp(float x, float& sg, float& sp) {
  float ax = fabsf(x);
  float e  = __expf(-ax);
  float p  = 1.0f + e;
  float rp = frcp(p);
  sg = (x >= 0.0f) ? rp : e * rp;
  sp = fmaxf(x, 0.0f) + __logf(p);
}
__device__ __forceinline__ float softplus_f(float x) {
  return fmaxf(x, 0.0f) + __logf(1.0f + __expf(-fabsf(x)));
}

union F4 { float4 v; float f[4]; };

__device__ __forceinline__ float4* p4(float* b, int m, int j) {
  return reinterpret_cast<float4*>(b + m * ROWSTR + j);
}
__device__ __forceinline__ const float4* p4c(const float* b, int m, int j) {
  return reinterpret_cast<const float4*>(b + m * ROWSTR + j);
}

// out[m][j] = sum_i xs[m][i] * Wg[i][j]
// Warp w owns output tile: ALL 32 rows x cols [32w, 32w+32).
// Lane (rg = lane&3, cg = lane>>2): rows m = rg + 4t (t=0..7), cols jc..jc+3.
// W load per i: one LDG.128 per lane; warp's 8 unique 16B chunks = ONE 128B line.
__device__ __forceinline__ void gemm32(const float* __restrict__ Wg,
                                       const float* __restrict__ xs,
                                       float acc[8][4]) {
  const int lane = threadIdx.x & 31;
  const int rg   = lane & 3;
  const int jc   = ((threadIdx.x >> 5) << 5) + ((lane >> 2) << 2);

  unsigned long long a2[8][2];
#pragma unroll
  for (int t = 0; t < 8; t++) { a2[t][0] = 0ull; a2[t][1] = 0ull; }

  const longlong2* W2 = reinterpret_cast<const longlong2*>(Wg);
  const float* xbase = xs + rg * ROWSTR;

#pragma unroll 2
  for (int i4 = 0; i4 < 64; i4++) {
    float4 xv[8];
#pragma unroll
    for (int t = 0; t < 8; t++)
      xv[t] = *reinterpret_cast<const float4*>(xbase + (4 * t) * ROWSTR + i4 * 4);
#pragma unroll
    for (int ii = 0; ii < 4; ii++) {
      const int i = i4 * 4 + ii;
      longlong2 wv = __ldg(&W2[(i * D + jc) >> 2]);
#pragma unroll
      for (int t = 0; t < 8; t++) {
        float xr = (ii == 0) ? xv[t].x : (ii == 1) ? xv[t].y
                 : (ii == 2) ? xv[t].z : xv[t].w;
        unsigned long long xx = pack2(xr);
        fma2(a2[t][0], xx, (unsigned long long)wv.x);
        fma2(a2[t][1], xx, (unsigned long long)wv.y);
      }
    }
  }
#pragma unroll
  for (int t = 0; t < 8; t++)
#pragma unroll
    for (int p = 0; p < 2; p++) {
      unsigned lo, hi;
      asm("mov.b64 {%0,%1}, %2;" : "=r"(lo), "=r"(hi) : "l"(a2[t][p]));
      acc[t][2 * p]     = __uint_as_float(lo);
      acc[t][2 * p + 1] = __uint_as_float(hi);
    }
}

// Buffers: slots {0,3} toggle z-role / softplus-role (also C-loop double buffer),
// slot 1 VHb (vh for B1 gemm only), slot 2 Hb, slot 4 Ub (gemm input workspace).
// vh / zn / cst are register-resident at owner positions (m=rg+4t, jc..jc+3).
__global__ void __launch_bounds__(NTHR, 1)
rhmc_kernel(const float* __restrict__ z0, const float* __restrict__ v0,
            const float* __restrict__ W, const float* __restrict__ bias,
            float* __restrict__ out) {
  extern __shared__ float smf[];
  float* B0  = smf;
  float* bsh = smf + NBUF * BUF_ELEMS;
  const int tid  = threadIdx.x;
  const int lane = tid & 31;
  const int rg   = lane & 3;
  const int jc   = ((tid >> 5) << 5) + ((lane >> 2) << 2);
  const int row0 = blockIdx.x * TILE_M;

  int zi = 0, spi = 3;
  float* VHb = B0 + 1 * BUF_ELEMS;
  float* Hb  = B0 + 2 * BUF_ELEMS;
  float* Ub  = B0 + 4 * BUF_ELEMS;

  bsh[tid] = bias[tid];
  for (int idx = tid; idx < TILE_M * D; idx += NTHR) {
    int m = idx >> 8, i = idx & 255;
    B0[zi * BUF_ELEMS + m * ROWSTR + i] = z0[(row0 + m) * D + i];
    VHb[m * ROWSTR + i] = v0[(row0 + m) * D + i];
  }
  __syncthreads();

  F4 bbv; bbv.v = *reinterpret_cast<const float4*>(bsh + jc);

  // vh -> registers (owner positions)
  float vhr[8][4];
#pragma unroll
  for (int t = 0; t < 8; t++) {
    F4 tmp; tmp.v = *p4c(VHb, rg + 4 * t, jc);
#pragma unroll
    for (int c = 0; c < 4; c++) vhr[t][c] = tmp.f[c];
  }

  float acc[8][4];

  // initial: a = z0@W + b -> sp into slot(spi), h into Hb
  gemm32(W, B0 + zi * BUF_ELEMS, acc);
  {
    float* Sb = B0 + spi * BUF_ELEMS;
#pragma unroll
    for (int t = 0; t < 8; t++) {
      const int m = rg + 4 * t;
      F4 osp, oh;
#pragma unroll
      for (int c = 0; c < 4; c++) {
        float x = acc[t][c] + bbv.f[c];
        float sg, sp; sigsp(x, sg, sp);
        osp.f[c] = sp;
        oh.f[c]  = 0.5f * sg * frcp(fmaxf(sp, 1e-12f));
      }
      *p4(Sb, m, jc) = osp.v;
      *p4(Hb, m, jc) = oh.v;
    }
  }

  for (int l = 0; l < L_STEPS; l++) {
    float* Zb = B0 + zi  * BUF_ELEMS;   // z
    float* Sb = B0 + spi * BUF_ELEMS;   // softplus(a(z))

    // top-of-step barrier: prior D2 gemm must finish reading Ub
    __syncthreads();

    // ---- A pre-pass: Ub = h*(sp*vh^2 - 1) (owner writes; h,sp are own values)
#pragma unroll
    for (int t = 0; t < 8; t++) {
      const int m = rg + 4 * t;
      F4 hv; hv.v = *p4c(Hb, m, jc);
      F4 sv; sv.v = *p4c(Sb, m, jc);
      F4 o;
#pragma unroll
      for (int c = 0; c < 4; c++)
        o.f[c] = hv.f[c] * (sv.f[c] * vhr[t][c] * vhr[t][c] - 1.0f);
      *p4(Ub, m, jc) = o.v;
    }
    __syncthreads();

    // ---- A: cumulative velocity iteration: vh <- vh - g/2 * (u @ W^T)
    for (int k = 0; k < NFX_IT; k++) {
      gemm32(g_WT, Ub, acc);
      __syncthreads();                  // all warps done reading Ub
#pragma unroll
      for (int t = 0; t < 8; t++)
#pragma unroll
        for (int c = 0; c < 4; c++) vhr[t][c] -= HGAM * acc[t][c];
      if (k < NFX_IT - 1) {
#pragma unroll
        for (int t = 0; t < 8; t++) {
          const int m = rg + 4 * t;
          F4 hv; hv.v = *p4c(Hb, m, jc);
          F4 sv; sv.v = *p4c(Sb, m, jc);
          F4 o;
#pragma unroll
          for (int c = 0; c < 4; c++)
            o.f[c] = hv.f[c] * (sv.f[c] * vhr[t][c] * vhr[t][c] - 1.0f);
          *p4(Ub, m, jc) = o.v;
        }
        __syncthreads();
      }
    }

    // publish vh for B1's gemm
#pragma unroll
    for (int t = 0; t < 8; t++) {
      F4 o;
#pragma unroll
      for (int c = 0; c < 4; c++) o.f[c] = vhr[t][c];
      *p4(VHb, rg + 4 * t, jc) = o.v;
    }
    __syncthreads();

    // ---- B1: c = vh@W + b -> w = sigmoid(c)/softplus(c) into Ub
    gemm32(W, VHb, acc);
#pragma unroll
    for (int t = 0; t < 8; t++) {
      F4 o;
#pragma unroll
      for (int c = 0; c < 4; c++) {
        float x = acc[t][c] + bbv.f[c];
        float sg, sp; sigsp(x, sg, sp);
        o.f[c] = sg * frcp(fmaxf(sp, 1e-12f));
      }
      *p4(Ub, rg + 4 * t, jc) = o.v;
    }
    __syncthreads();

    // ---- B2: rr = w@W^T ; cst = g/2*(sp(z)*vh - rr) (regs); zn=z (regs + Sb)
    gemm32(g_WT, Ub, acc);
    float cstr[8][4], znr[8][4];
#pragma unroll
    for (int t = 0; t < 8; t++) {
      const int m = rg + 4 * t;
      F4 ss; ss.v = *p4c(Sb, m, jc);    // own sp(z)
      F4 zz; zz.v = *p4c(Zb, m, jc);    // own z
      F4 oz;
#pragma unroll
      for (int c = 0; c < 4; c++) {
        cstr[t][c] = HGAM * (ss.f[c] * vhr[t][c] - acc[t][c]);
        znr[t][c]  = zz.f[c];
        oz.f[c]    = zz.f[c];
      }
      *p4(Sb, m, jc) = oz.v;            // zn buffer starts at z
    }
    __syncthreads();

    // ---- C: cumulative position iteration, double-buffered between Sb/Zb:
    //         zn += cst + g/2 * softplus(zn@W+b) * vh
    {
      float* cur = Sb;
      float* alt = Zb;
      for (int k = 0; k < NFX_IT; k++) {
        gemm32(W, cur, acc);
#pragma unroll
        for (int t = 0; t < 8; t++) {
          F4 o;
#pragma unroll
          for (int c = 0; c < 4; c++) {
            float sp = softplus_f(acc[t][c] + bbv.f[c]);
            znr[t][c] += cstr[t][c] + HGAM * sp * vhr[t][c];
            o.f[c] = znr[t][c];
          }
          *p4(alt, rg + 4 * t, jc) = o.v;
        }
        __syncthreads();
        float* tmp = cur; cur = alt; alt = tmp;
      }
      // NFX_IT even -> final zn lives in Sb
    }

    // ---- D1: a(z_new) -> sp into Zb-slot, h into Hb, u into Ub
    gemm32(W, Sb, acc);
#pragma unroll
    for (int t = 0; t < 8; t++) {
      const int m = rg + 4 * t;
      F4 osp, oh, ou;
#pragma unroll
      for (int c = 0; c < 4; c++) {
        float x = acc[t][c] + bbv.f[c];
        float sg, sp; sigsp(x, sg, sp);
        float h = 0.5f * sg * frcp(fmaxf(sp, 1e-12f));
        osp.f[c] = sp;
        oh.f[c]  = h;
        ou.f[c]  = h * (sp * vhr[t][c] * vhr[t][c] - 1.0f);
      }
      *p4(Zb, m, jc) = osp.v;   // Zb-slot becomes sp-role after rotation
      *p4(Hb, m, jc) = oh.v;
      *p4(Ub, m, jc) = ou.v;
    }
    __syncthreads();

    // ---- D2: v_new = vh - g/2 * (u@W^T)  (registers only)
    gemm32(g_WT, Ub, acc);
#pragma unroll
    for (int t = 0; t < 8; t++)
#pragma unroll
      for (int c = 0; c < 4; c++) vhr[t][c] -= HGAM * acc[t][c];
    // no trailing sync: next step's top-of-step barrier covers Ub reuse

    int t2 = zi; zi = spi; spi = t2;
  }
  __syncthreads();

  // ---- output: stack([z_f, v_f]); z from smem (coalesced), v from registers
  float* Zf = B0 + zi * BUF_ELEMS;
  for (int idx = tid; idx < TILE_M * D; idx += NTHR) {
    int m = idx >> 8, i = idx & 255;
    out[(row0 + m) * D + i] = Zf[m * ROWSTR + i];
  }
#pragma unroll
  for (int t = 0; t < 8; t++) {
    F4 o;
#pragma unroll
    for (int c = 0; c < 4; c++) o.f[c] = vhr[t][c];
    *reinterpret_cast<float4*>(out + BD * D + (row0 + rg + 4 * t) * D + jc) = o.v;
  }
}

extern "C" void kernel_launch(void* const* d_in, const int* in_sizes, int n_in,
                              void* d_out, int out_size) {
  const float* z0   = (const float*)d_in[0];
  const float* v0   = (const float*)d_in[1];
  const float* W    = (const float*)d_in[2];
  const float* bias = (const float*)d_in[3];
  float* out = (float*)d_out;

  cudaFuncSetAttribute(rhmc_kernel, cudaFuncAttributeMaxDynamicSharedMemorySize,
                       SMEM_BYTES);

  wt_kernel<<<D, D>>>(W);
  rhmc_kernel<<<NCTA, NTHR, SMEM_BYTES>>>(z0, v0, W, bias, out);
}

// round 7
// speedup vs baseline: 1.3600x; 1.0005x over previous
#include <cuda_runtime.h>
#include <cstdint>

#define D        256
#define BD       16384
#define TILE_M   32
#define ROWSTR   264            // 256 + 8 floats pad
#define NTHR     256
#define NCTA     (BD / TILE_M)  // 512
#define L_STEPS  6
#define NFX_IT   8
#define HGAM     0.005f         // gamma/2
#define BUF_ELEMS (TILE_M * ROWSTR)
#define NBUF     5
#define SMEM_BYTES ((NBUF * BUF_ELEMS + D) * 4)

__device__ float g_WT[D * D];

__global__ void wt_kernel(const float* __restrict__ W) {
  int j = blockIdx.x, i = threadIdx.x;
  g_WT[j * D + i] = W[i * D + j];
}

__device__ __forceinline__ float frcp(float x) {
  float r; asm("rcp.approx.f32 %0, %1;" : "=f"(r) : "f"(x)); return r;
}
__device__ __forceinline__ unsigned long long pack2(float x) {
  unsigned long long r; unsigned u = __float_as_uint(x);
  asm("mov.b64 %0, {%1, %1};" : "=l"(r) : "r"(u)); return r;
}
__device__ __forceinline__ void fma2(unsigned long long& d, unsigned long long a,
                                     unsigned long long b) {
  asm("fma.rn.f32x2 %0, %1, %2, %0;" : "+l"(d) : "l"(a), "l"(b));
}

// stable sigmoid + softplus
__device__ __forceinline__ void sigsp(float x, float& sg, float& sp) {
  float ax = fabsf(x);
  float e  = __expf(-ax);
  float p  = 1.0f + e;
  float rp = frcp(p);
  sg = (x >= 0.0f) ? rp : e * rp;
  sp = fmaxf(x, 0.0f) + __logf(p);
}
__device__ __forceinline__ float softplus_f(float x) {
  return fmaxf(x, 0.0f) + __logf(1.0f + __expf(-fabsf(x)));
}

union F4 { float4 v; float f[4]; };

__device__ __forceinline__ float4* p4(float* b, int m, int j) {
  return reinterpret_cast<float4*>(b + m * ROWSTR + j);
}
__device__ __forceinline__ const float4* p4c(const float* b, int m, int j) {
  return reinterpret_cast<const float4*>(b + m * ROWSTR + j);
}

// out[m][j] = sum_i xs[m][i] * Wg[i][j]
// Warp w owns output tile: ALL 32 rows x cols [32w, 32w+32).
// Lane (rg = lane&3, cg = lane>>2): rows m = rg + 4t (t=0..7), cols jc..jc+3.
// W load per i: one LDG.128 per lane; warp's 8 unique 16B chunks = ONE 128B line.
__device__ __forceinline__ void gemm32(const float* __restrict__ Wg,
                                       const float* __restrict__ xs,
                                       float acc[8][4]) {
  const int lane = threadIdx.x & 31;
  const int rg   = lane & 3;
  const int jc   = ((threadIdx.x >> 5) << 5) + ((lane >> 2) << 2);

  unsigned long long a2[8][2];
#pragma unroll
  for (int t = 0; t < 8; t++) { a2[t][0] = 0ull; a2[t][1] = 0ull; }

  const longlong2* W2 = reinterpret_cast<const longlong2*>(Wg);
  const float* xbase = xs + rg * ROWSTR;

#pragma unroll 2
  for (int i4 = 0; i4 < 64; i4++) {
    float4 xv[8];
#pragma unroll
    for (int t = 0; t < 8; t++)
      xv[t] = *reinterpret_cast<const float4*>(xbase + (4 * t) * ROWSTR + i4 * 4);
#pragma unroll
    for (int ii = 0; ii < 4; ii++) {
      const int i = i4 * 4 + ii;
      longlong2 wv = __ldg(&W2[(i * D + jc) >> 2]);
#pragma unroll
      for (int t = 0; t < 8; t++) {
        float xr = (ii == 0) ? xv[t].x : (ii == 1) ? xv[t].y
                 : (ii == 2) ? xv[t].z : xv[t].w;
        unsigned long long xx = pack2(xr);
        fma2(a2[t][0], xx, (unsigned long long)wv.x);
        fma2(a2[t][1], xx, (unsigned long long)wv.y);
      }
    }
  }
#pragma unroll
  for (int t = 0; t < 8; t++)
#pragma unroll
    for (int p = 0; p < 2; p++) {
      unsigned lo, hi;
      asm("mov.b64 {%0,%1}, %2;" : "=r"(lo), "=r"(hi) : "l"(a2[t][p]));
      acc[t][2 * p]     = __uint_as_float(lo);
      acc[t][2 * p + 1] = __uint_as_float(hi);
    }
}

// Buffers: slots {0,3} toggle z-role / softplus-role (also C-loop double buffer),
// slot 1 VHb (vh for B1 gemm only), slot 2 Hb, slot 4 Ub (gemm input workspace).
// vh / zn / cst are register-resident at owner positions (m=rg+4t, jc..jc+3).
__global__ void __launch_bounds__(NTHR, 1)
rhmc_kernel(const float* __restrict__ z0, const float* __restrict__ v0,
            const float* __restrict__ W, const float* __restrict__ bias,
            float* __restrict__ out) {
  extern __shared__ float smf[];
  float* B0  = smf;
  float* bsh = smf + NBUF * BUF_ELEMS;
  const int tid  = threadIdx.x;
  const int lane = tid & 31;
  const int rg   = lane & 3;
  const int jc   = ((tid >> 5) << 5) + ((lane >> 2) << 2);
  const int row0 = blockIdx.x * TILE_M;

  int zi = 0, spi = 3;
  float* VHb = B0 + 1 * BUF_ELEMS;
  float* Hb  = B0 + 2 * BUF_ELEMS;
  float* Ub  = B0 + 4 * BUF_ELEMS;

  bsh[tid] = bias[tid];
  for (int idx = tid; idx < TILE_M * D; idx += NTHR) {
    int m = idx >> 8, i = idx & 255;
    B0[zi * BUF_ELEMS + m * ROWSTR + i] = z0[(row0 + m) * D + i];
    VHb[m * ROWSTR + i] = v0[(row0 + m) * D + i];
  }
  __syncthreads();

  F4 bbv; bbv.v = *reinterpret_cast<const float4*>(bsh + jc);

  // vh -> registers (owner positions)
  float vhr[8][4];
#pragma unroll
  for (int t = 0; t < 8; t++) {
    F4 tmp; tmp.v = *p4c(VHb, rg + 4 * t, jc);
#pragma unroll
    for (int c = 0; c < 4; c++) vhr[t][c] = tmp.f[c];
  }

  float acc[8][4];

  // initial: a = z0@W + b -> sp into slot(spi), h into Hb
  gemm32(W, B0 + zi * BUF_ELEMS, acc);
  {
    float* Sb = B0 + spi * BUF_ELEMS;
#pragma unroll
    for (int t = 0; t < 8; t++) {
      const int m = rg + 4 * t;
      F4 osp, oh;
#pragma unroll
      for (int c = 0; c < 4; c++) {
        float x = acc[t][c] + bbv.f[c];
        float sg, sp; sigsp(x, sg, sp);
        osp.f[c] = sp;
        oh.f[c]  = 0.5f * sg * frcp(fmaxf(sp, 1e-12f));
      }
      *p4(Sb, m, jc) = osp.v;
      *p4(Hb, m, jc) = oh.v;
    }
  }

  for (int l = 0; l < L_STEPS; l++) {
    float* Zb = B0 + zi  * BUF_ELEMS;   // z
    float* Sb = B0 + spi * BUF_ELEMS;   // softplus(a(z))

    // top-of-step barrier: prior D2 gemm must finish reading Ub
    __syncthreads();

    // ---- A pre-pass: Ub = h*(sp*vh^2 - 1) (owner writes; h,sp are own values)
#pragma unroll
    for (int t = 0; t < 8; t++) {
      const int m = rg + 4 * t;
      F4 hv; hv.v = *p4c(Hb, m, jc);
      F4 sv; sv.v = *p4c(Sb, m, jc);
      F4 o;
#pragma unroll
      for (int c = 0; c < 4; c++)
        o.f[c] = hv.f[c] * (sv.f[c] * vhr[t][c] * vhr[t][c] - 1.0f);
      *p4(Ub, m, jc) = o.v;
    }
    __syncthreads();

    // ---- A: cumulative velocity iteration: vh <- vh - g/2 * (u @ W^T)
    for (int k = 0; k < NFX_IT; k++) {
      gemm32(g_WT, Ub, acc);
      __syncthreads();                  // all warps done reading Ub
#pragma unroll
      for (int t = 0; t < 8; t++)
#pragma unroll
        for (int c = 0; c < 4; c++) vhr[t][c] -= HGAM * acc[t][c];
      if (k < NFX_IT - 1) {
#pragma unroll
        for (int t = 0; t < 8; t++) {
          const int m = rg + 4 * t;
          F4 hv; hv.v = *p4c(Hb, m, jc);
          F4 sv; sv.v = *p4c(Sb, m, jc);
          F4 o;
#pragma unroll
          for (int c = 0; c < 4; c++)
            o.f[c] = hv.f[c] * (sv.f[c] * vhr[t][c] * vhr[t][c] - 1.0f);
          *p4(Ub, m, jc) = o.v;
        }
        __syncthreads();
      }
    }

    // publish vh for B1's gemm
#pragma unroll
    for (int t = 0; t < 8; t++) {
      F4 o;
#pragma unroll
      for (int c = 0; c < 4; c++) o.f[c] = vhr[t][c];
      *p4(VHb, rg + 4 * t, jc) = o.v;
    }
    __syncthreads();

    // ---- B1: c = vh@W + b -> w = sigmoid(c)/softplus(c) into Ub
    gemm32(W, VHb, acc);
#pragma unroll
    for (int t = 0; t < 8; t++) {
      F4 o;
#pragma unroll
      for (int c = 0; c < 4; c++) {
        float x = acc[t][c] + bbv.f[c];
        float sg, sp; sigsp(x, sg, sp);
        o.f[c] = sg * frcp(fmaxf(sp, 1e-12f));
      }
      *p4(Ub, rg + 4 * t, jc) = o.v;
    }
    __syncthreads();

    // ---- B2: rr = w@W^T ; cst = g/2*(sp(z)*vh - rr) (regs); zn=z (regs + Sb)
    gemm32(g_WT, Ub, acc);
    float cstr[8][4], znr[8][4];
#pragma unroll
    for (int t = 0; t < 8; t++) {
      const int m = rg + 4 * t;
      F4 ss; ss.v = *p4c(Sb, m, jc);    // own sp(z)
      F4 zz; zz.v = *p4c(Zb, m, jc);    // own z
      F4 oz;
#pragma unroll
      for (int c = 0; c < 4; c++) {
        cstr[t][c] = HGAM * (ss.f[c] * vhr[t][c] - acc[t][c]);
        znr[t][c]  = zz.f[c];
        oz.f[c]    = zz.f[c];
      }
      *p4(Sb, m, jc) = oz.v;            // zn buffer starts at z
    }
    __syncthreads();

    // ---- C: cumulative position iteration, double-buffered between Sb/Zb:
    //         zn += cst + g/2 * softplus(zn@W+b) * vh
    {
      float* cur = Sb;
      float* alt = Zb;
      for (int k = 0; k < NFX_IT; k++) {
        gemm32(W, cur, acc);
#pragma unroll
        for (int t = 0; t < 8; t++) {
          F4 o;
#pragma unroll
          for (int c = 0; c < 4; c++) {
            float sp = softplus_f(acc[t][c] + bbv.f[c]);
            znr[t][c] += cstr[t][c] + HGAM * sp * vhr[t][c];
            o.f[c] = znr[t][c];
          }
          *p4(alt, rg + 4 * t, jc) = o.v;
        }
        __syncthreads();
        float* tmp = cur; cur = alt; alt = tmp;
      }
      // NFX_IT even -> final zn lives in Sb
    }

    // ---- D1: a(z_new) -> sp into Zb-slot, h into Hb, u into Ub
    gemm32(W, Sb, acc);
#pragma unroll
    for (int t = 0; t < 8; t++) {
      const int m = rg + 4 * t;
      F4 osp, oh, ou;
#pragma unroll
      for (int c = 0; c < 4; c++) {
        float x = acc[t][c] + bbv.f[c];
        float sg, sp; sigsp(x, sg, sp);
        float h = 0.5f * sg * frcp(fmaxf(sp, 1e-12f));
        osp.f[c] = sp;
        oh.f[c]  = h;
        ou.f[c]  = h * (sp * vhr[t][c] * vhr[t][c] - 1.0f);
      }
      *p4(Zb, m, jc) = osp.v;   // Zb-slot becomes sp-role after rotation
      *p4(Hb, m, jc) = oh.v;
      *p4(Ub, m, jc) = ou.v;
    }
    __syncthreads();

    // ---- D2: v_new = vh - g/2 * (u@W^T)  (registers only)
    gemm32(g_WT, Ub, acc);
#pragma unroll
    for (int t = 0; t < 8; t++)
#pragma unroll
      for (int c = 0; c < 4; c++) vhr[t][c] -= HGAM * acc[t][c];
    // no trailing sync: next step's top-of-step barrier covers Ub reuse

    int t2 = zi; zi = spi; spi = t2;
  }
  __syncthreads();

  // ---- output: stack([z_f, v_f]); z from smem (coalesced), v from registers
  float* Zf = B0 + zi * BUF_ELEMS;
  for (int idx = tid; idx < TILE_M * D; idx += NTHR) {
    int m = idx >> 8, i = idx & 255;
    out[(row0 + m) * D + i] = Zf[m * ROWSTR + i];
  }
#pragma unroll
  for (int t = 0; t < 8; t++) {
    F4 o;
#pragma unroll
    for (int c = 0; c < 4; c++) o.f[c] = vhr[t][c];
    *reinterpret_cast<float4*>(out + BD * D + (row0 + rg + 4 * t) * D + jc) = o.v;
  }
}

extern "C" void kernel_launch(void* const* d_in, const int* in_sizes, int n_in,
                              void* d_out, int out_size) {
  const float* z0   = (const float*)d_in[0];
  const float* v0   = (const float*)d_in[1];
  const float* W    = (const float*)d_in[2];
  const float* bias = (const float*)d_in[3];
  float* out = (float*)d_out;

  cudaFuncSetAttribute(rhmc_kernel, cudaFuncAttributeMaxDynamicSharedMemorySize,
                       SMEM_BYTES);

  wt_kernel<<<D, D>>>(W);
  rhmc_kernel<<<NCTA, NTHR, SMEM_BYTES>>>(z0, v0, W, bias, out);
}